// round 4
// baseline (speedup 1.0000x reference)
#include <cuda_runtime.h>
#include <cuda_bf16.h>
#include <cstdint>

// ============================================================================
// Problem constants
// ============================================================================
constexpr int N_ROWS  = 32768;
constexpr int K_PROTO = 2048;
constexpr int D_DIM   = 512;

constexpr int M_TILE = 128;     // CTA rows
constexpr int N_TILE = 128;     // CTA cols
constexpr int K_CHUNK = 64;     // bf16 per K chunk = 128 bytes per row
constexpr int NUM_CHUNKS = D_DIM / K_CHUNK;   // 8
constexpr int N_TILES = K_PROTO / N_TILE;     // 16
constexpr int M_TILES = N_ROWS / M_TILE;      // 256
constexpr int N_SLICES = K_PROTO / 32;        // 64 (per-warp col slice partials)

// SMEM: A 2 bufs of 128*128B, B same
constexpr int A_BUF_BYTES = M_TILE * 128;     // 16384
constexpr int B_BUF_BYTES = N_TILE * 128;     // 16384
constexpr int SMEM_A = 0;
constexpr int SMEM_B = 2 * A_BUF_BYTES;       // 32768
constexpr int SMEM_TOTAL = SMEM_B + 2 * B_BUF_BYTES;  // 65536

// ============================================================================
// Device scratch (allocation-free)
// ============================================================================
__device__ __nv_bfloat16 g_fbf16[(size_t)N_ROWS * D_DIM];
__device__ __nv_bfloat16 g_pbf16[(size_t)K_PROTO * D_DIM];
__device__ float g_f2[N_ROWS];
__device__ float g_p2[K_PROTO];
__device__ float g_part[(size_t)N_ROWS * N_SLICES];
__device__ float g_rowinv[N_ROWS];

// ============================================================================
// Helpers
// ============================================================================
__device__ __forceinline__ uint32_t smem_u32(const void* p) {
    uint32_t a;
    asm("{ .reg .u64 t; cvta.to.shared.u64 t, %1; cvt.u32.u64 %0, t; }"
        : "=r"(a) : "l"(p));
    return a;
}

__device__ __forceinline__ uint32_t sw128(uint32_t off) {
    return off ^ ((off >> 3) & 0x70);
}

__device__ __forceinline__ void cp_async16(uint32_t dst, const void* src) {
    asm volatile("cp.async.cg.shared.global [%0], [%1], 16;"
                 :: "r"(dst), "l"(src) : "memory");
}
__device__ __forceinline__ void cp_commit() {
    asm volatile("cp.async.commit_group;" ::: "memory");
}
template <int N>
__device__ __forceinline__ void cp_wait() {
    asm volatile("cp.async.wait_group %0;" :: "n"(N) : "memory");
}

__device__ __forceinline__ void ldmatrix_x4(uint32_t* r, uint32_t addr) {
    asm volatile("ldmatrix.sync.aligned.m8n8.x4.shared.b16 {%0,%1,%2,%3}, [%4];"
                 : "=r"(r[0]), "=r"(r[1]), "=r"(r[2]), "=r"(r[3]) : "r"(addr));
}
__device__ __forceinline__ void ldmatrix_x2(uint32_t* r, uint32_t addr) {
    asm volatile("ldmatrix.sync.aligned.m8n8.x2.shared.b16 {%0,%1}, [%2];"
                 : "=r"(r[0]), "=r"(r[1]) : "r"(addr));
}

__device__ __forceinline__ void mma_bf16(float* c, const uint32_t* a, const uint32_t* b) {
    asm volatile(
        "mma.sync.aligned.m16n8k16.row.col.f32.bf16.bf16.f32 "
        "{%0,%1,%2,%3}, {%4,%5,%6,%7}, {%8,%9}, {%0,%1,%2,%3};"
        : "+f"(c[0]), "+f"(c[1]), "+f"(c[2]), "+f"(c[3])
        : "r"(a[0]), "r"(a[1]), "r"(a[2]), "r"(a[3]), "r"(b[0]), "r"(b[1]));
}

// ============================================================================
// Kernel 0/1: fp32 -> bf16 + squared norms (one warp per row)
// ============================================================================
__global__ void prep_features(const float* __restrict__ f) {
    int row  = blockIdx.x * 8 + (threadIdx.x >> 5);
    int lane = threadIdx.x & 31;
    const float* src = f + (size_t)row * D_DIM;
    __nv_bfloat16* dst = g_fbf16 + (size_t)row * D_DIM;
    float s = 0.f;
#pragma unroll
    for (int j = 0; j < D_DIM / 32; j++) {
        float v = src[j * 32 + lane];
        s += v * v;
        dst[j * 32 + lane] = __float2bfloat16(v);
    }
#pragma unroll
    for (int o = 16; o; o >>= 1) s += __shfl_xor_sync(0xFFFFFFFFu, s, o);
    if (lane == 0) g_f2[row] = s;
}

__global__ void prep_protos(const float* __restrict__ p) {
    int row  = blockIdx.x * 8 + (threadIdx.x >> 5);
    int lane = threadIdx.x & 31;
    const float* src = p + (size_t)row * D_DIM;
    __nv_bfloat16* dst = g_pbf16 + (size_t)row * D_DIM;
    float s = 0.f;
#pragma unroll
    for (int j = 0; j < D_DIM / 32; j++) {
        float v = src[j * 32 + lane];
        s += v * v;
        dst[j * 32 + lane] = __float2bfloat16(v);
    }
#pragma unroll
    for (int o = 16; o; o >>= 1) s += __shfl_xor_sync(0xFFFFFFFFu, s, o);
    if (lane == 0) g_p2[row] = s;
}

// ============================================================================
// Kernel 2: bf16 mma.sync GEMM + fused epilogue exp(1/(1+dist))
// grid = (N_TILES=16, M_TILES=256), 256 threads (8 warps, 2x4)
// ============================================================================
__global__ void __launch_bounds__(256, 1)
gemm_sim_kernel(float* __restrict__ out) {
    extern __shared__ char smem[];
    const uint32_t smem_base = smem_u32(smem);
    const int tid  = threadIdx.x;
    const int wid  = tid >> 5;
    const int lane = tid & 31;
    const int warp_m = wid >> 2;     // 0..1
    const int warp_n = wid & 3;      // 0..3

    const int n_tile = blockIdx.x;   // 0..15
    const int m_tile = blockIdx.y;   // 0..255

    const __nv_bfloat16* aBase = g_fbf16 + (size_t)m_tile * M_TILE * D_DIM;
    const __nv_bfloat16* bBase = g_pbf16 + (size_t)n_tile * N_TILE * D_DIM;

    // ---- async load of one K chunk into a buffer ----
    auto load_chunk = [&](int s, int buf) {
        // A: 128 rows x 8 x 16B
        {
            uint32_t dst = smem_base + SMEM_A + buf * A_BUF_BYTES;
            const __nv_bfloat16* src = aBase + s * K_CHUNK;
#pragma unroll
            for (int j = 0; j < 4; ++j) {
                int i = tid + j * 256;           // 0..1023
                int r = i >> 3, c = i & 7;
                cp_async16(dst + sw128((uint32_t)(r * 128 + c * 16)),
                           src + (size_t)r * D_DIM + c * 8);
            }
        }
        // B: 128 rows x 8 x 16B
        {
            uint32_t dst = smem_base + SMEM_B + buf * B_BUF_BYTES;
            const __nv_bfloat16* src = bBase + s * K_CHUNK;
#pragma unroll
            for (int j = 0; j < 4; ++j) {
                int i = tid + j * 256;
                int r = i >> 3, c = i & 7;
                cp_async16(dst + sw128((uint32_t)(r * 128 + c * 16)),
                           src + (size_t)r * D_DIM + c * 8);
            }
        }
    };

    float acc[4][4][4];
#pragma unroll
    for (int mi = 0; mi < 4; ++mi)
#pragma unroll
        for (int ni = 0; ni < 4; ++ni)
#pragma unroll
            for (int q = 0; q < 4; ++q) acc[mi][ni][q] = 0.f;

    load_chunk(0, 0);
    cp_commit();

    for (int s = 0; s < NUM_CHUNKS; ++s) {
        if (s + 1 < NUM_CHUNKS) {
            load_chunk(s + 1, (s + 1) & 1);
            cp_commit();
            cp_wait<1>();
        } else {
            cp_wait<0>();
        }
        __syncthreads();

        const uint32_t aBuf = smem_base + SMEM_A + (s & 1) * A_BUF_BYTES;
        const uint32_t bBuf = smem_base + SMEM_B + (s & 1) * B_BUF_BYTES;

#pragma unroll
        for (int ks = 0; ks < 4; ++ks) {
            uint32_t afrag[4][4], bfrag[4][2];
#pragma unroll
            for (int mi = 0; mi < 4; ++mi) {
                int row = warp_m * 64 + mi * 16 + (lane & 15);
                int kb  = ks * 32 + (lane >> 4) * 16;
                ldmatrix_x4(afrag[mi], aBuf + sw128((uint32_t)(row * 128 + kb)));
            }
#pragma unroll
            for (int ni = 0; ni < 4; ++ni) {
                int row = warp_n * 32 + ni * 8 + (lane & 7);
                int kb  = ks * 32 + ((lane >> 3) & 1) * 16;
                ldmatrix_x2(bfrag[ni], bBuf + sw128((uint32_t)(row * 128 + kb)));
            }
#pragma unroll
            for (int mi = 0; mi < 4; ++mi)
#pragma unroll
                for (int ni = 0; ni < 4; ++ni)
                    mma_bf16(acc[mi][ni], afrag[mi], bfrag[ni]);
        }
        __syncthreads();
    }

    // ---- fused epilogue ----
    const int groupID = lane >> 2;
    const int tq      = lane & 3;
    const int colbase = n_tile * N_TILE + warp_n * 32;
    const int slice   = n_tile * 4 + warp_n;

    float p2v[4][2];
#pragma unroll
    for (int ni = 0; ni < 4; ++ni) {
        int c0 = colbase + ni * 8 + tq * 2;
        p2v[ni][0] = __ldg(&g_p2[c0]);
        p2v[ni][1] = __ldg(&g_p2[c0 + 1]);
    }

#pragma unroll
    for (int mi = 0; mi < 4; ++mi) {
        int r0 = m_tile * M_TILE + warp_m * 64 + mi * 16 + groupID;
        int r1 = r0 + 8;
        float f20 = __ldg(&g_f2[r0]);
        float f21 = __ldg(&g_f2[r1]);
        float sum0 = 0.f, sum1 = 0.f;
#pragma unroll
        for (int ni = 0; ni < 4; ++ni) {
            int c0 = colbase + ni * 8 + tq * 2;
            float e[4];
#pragma unroll
            for (int q = 0; q < 4; ++q) {
                float f2x = (q < 2) ? f20 : f21;
                float p2x = p2v[ni][q & 1];
                float sq  = fmaxf(f2x + p2x - 2.0f * acc[mi][ni][q], 0.0f);
                float sim = 1.0f / (1.0f + sqrtf(sq));
                e[q] = __expf(sim);
            }
            sum0 += e[0] + e[1];
            sum1 += e[2] + e[3];
            *reinterpret_cast<float2*>(out + (size_t)r0 * K_PROTO + c0) =
                make_float2(e[0], e[1]);
            *reinterpret_cast<float2*>(out + (size_t)r1 * K_PROTO + c0) =
                make_float2(e[2], e[3]);
        }
        sum0 += __shfl_xor_sync(0xFFFFFFFFu, sum0, 1);
        sum0 += __shfl_xor_sync(0xFFFFFFFFu, sum0, 2);
        sum1 += __shfl_xor_sync(0xFFFFFFFFu, sum1, 1);
        sum1 += __shfl_xor_sync(0xFFFFFFFFu, sum1, 2);
        if (tq == 0) {
            g_part[(size_t)r0 * N_SLICES + slice] = sum0;
            g_part[(size_t)r1 * N_SLICES + slice] = sum1;
        }
    }
}

// ============================================================================
// Kernel 3a: rowinv = 1/sum (one warp per row)
// ============================================================================
__global__ void finish_rows() {
    int row  = blockIdx.x * 8 + (threadIdx.x >> 5);
    int lane = threadIdx.x & 31;
    const float* p = g_part + (size_t)row * N_SLICES;
    float s = p[lane] + p[lane + 32];
#pragma unroll
    for (int o = 16; o; o >>= 1) s += __shfl_xor_sync(0xFFFFFFFFu, s, o);
    if (lane == 0) g_rowinv[row] = 1.0f / s;
}

// ============================================================================
// Kernel 3b: out *= rowinv[row]
// ============================================================================
__global__ void scale_out(float4* __restrict__ out) {
    size_t i = (size_t)blockIdx.x * blockDim.x + threadIdx.x;
    float inv = g_rowinv[i >> 9];          // 512 float4 per row
    float4 v = out[i];
    v.x *= inv; v.y *= inv; v.z *= inv; v.w *= inv;
    out[i] = v;
}

// ============================================================================
// Launch
// ============================================================================
extern "C" void kernel_launch(void* const* d_in, const int* in_sizes, int n_in,
                              void* d_out, int out_size) {
    const float* features   = (const float*)d_in[0];
    const float* prototypes = (const float*)d_in[1];
    if (n_in >= 2 && in_sizes[0] == K_PROTO * D_DIM && in_sizes[1] == N_ROWS * D_DIM) {
        features   = (const float*)d_in[1];
        prototypes = (const float*)d_in[0];
    }
    float* out = (float*)d_out;

    cudaFuncSetAttribute(gemm_sim_kernel,
                         cudaFuncAttributeMaxDynamicSharedMemorySize, SMEM_TOTAL);

    prep_features<<<N_ROWS / 8, 256>>>(features);
    prep_protos<<<K_PROTO / 8, 256>>>(prototypes);
    gemm_sim_kernel<<<dim3(N_TILES, M_TILES), 256, SMEM_TOTAL>>>(out);
    finish_rows<<<N_ROWS / 8, 256>>>();
    scale_out<<<(size_t)N_ROWS * K_PROTO / 4 / 256, 256>>>((float4*)out);
}